// round 3
// baseline (speedup 1.0000x reference)
#include <cuda_runtime.h>
#include <cuda_fp16.h>
#include <cstdint>
#include <cstddef>

// ---------------- problem constants ----------------
#define TOKENS 8192
#define IN_F   4096
#define OUT_F  11008

// ---------------- GEMM tiling ----------------
#define BM 128
#define BN 128
#define BK 64
#define STAGES 3
#define KITERS (IN_F / BK)          // 64

// SMEM layout (byte offsets from 1024-aligned base)
#define OFF_A      0                         // 3 x 16384
#define OFF_B      (OFF_A + STAGES * 16384)  // 3 x 16384
#define OFF_RAW    (OFF_B + STAGES * 16384)  // 3 x 4096  (8 kp-rows x 128 n int32)
#define OFF_SC     (OFF_RAW + STAGES * 4096) // 3 x 512   (128 scales fp32)
#define OFF_QZ     (OFF_SC + STAGES * 512)   // 3 x 64    (16 int32)
#define SMEM_USED  (OFF_QZ + STAGES * 64)    // 112320
#define SMEM_BYTES (SMEM_USED + 1024)        // align slack -> 113344 (2 CTAs/SM)

// ---------------- scratch (static device global; no allocation) ----------------
__device__ __align__(1024) __half g_X[(size_t)TOKENS * IN_F]; // x fp16: [m][k], 67 MB

// ---------------- PTX helpers (baseline sm_80+ only) ----------------
__device__ __forceinline__ uint32_t smem_u32(const void* p) {
    uint32_t a;
    asm("{ .reg .u64 t; cvta.to.shared.u64 t, %1; cvt.u32.u64 %0, t; }" : "=r"(a) : "l"(p));
    return a;
}
__device__ __forceinline__ void cp_async16(uint32_t dst, const void* src) {
    asm volatile("cp.async.cg.shared.global [%0], [%1], 16;" :: "r"(dst), "l"(src) : "memory");
}
__device__ __forceinline__ void cp_commit() {
    asm volatile("cp.async.commit_group;" ::: "memory");
}
template <int N> __device__ __forceinline__ void cp_wait() {
    asm volatile("cp.async.wait_group %0;" :: "n"(N) : "memory");
}
__device__ __forceinline__ void ldsm_x4(uint32_t& r0, uint32_t& r1, uint32_t& r2, uint32_t& r3,
                                        uint32_t addr) {
    asm volatile("ldmatrix.sync.aligned.m8n8.x4.shared.b16 {%0,%1,%2,%3}, [%4];"
                 : "=r"(r0), "=r"(r1), "=r"(r2), "=r"(r3) : "r"(addr));
}
__device__ __forceinline__ void sts128(uint32_t addr, uint32_t r0, uint32_t r1,
                                       uint32_t r2, uint32_t r3) {
    asm volatile("st.shared.v4.b32 [%0], {%1,%2,%3,%4};"
                 :: "r"(addr), "r"(r0), "r"(r1), "r"(r2), "r"(r3) : "memory");
}
__device__ __forceinline__ void mma16816(float* c, const uint32_t* a, const uint32_t* b) {
    asm volatile(
        "mma.sync.aligned.m16n8k16.row.col.f32.f16.f16.f32 "
        "{%0,%1,%2,%3}, {%4,%5,%6,%7}, {%8,%9}, {%0,%1,%2,%3};"
        : "+f"(c[0]), "+f"(c[1]), "+f"(c[2]), "+f"(c[3])
        : "r"(a[0]), "r"(a[1]), "r"(a[2]), "r"(a[3]), "r"(b[0]), "r"(b[1]));
}

// SW128 swizzle on byte offset within a tile (128B rows)
#define SWZ(o) ((o) ^ (((o) >> 3) & 0x70))

// ---------------- kernel 1: x fp32 -> fp16 ----------------
__global__ void __launch_bounds__(256) xconv_kernel(const float* __restrict__ x) {
    size_t i = (size_t)blockIdx.x * blockDim.x + threadIdx.x;  // over TOKENS*IN_F/4, exact
    float4 v = ((const float4*)x)[i];
    union { __half2 h[2]; uint2 u; } r;
    r.h[0] = __floats2half2_rn(v.x, v.y);
    r.h[1] = __floats2half2_rn(v.z, v.w);
    ((uint2*)g_X)[i] = r.u;
}

// ---------------- kernel 2: fused dequant + pipelined HMMA GEMM ----------------
// Issue one cp.async group for stage kt: A tile (fp16), raw qweight, scales, qzeros.
__device__ __forceinline__ void issue_group(int kt, uint32_t sb, const __half* gA,
                                            const int* qw, const int* qz,
                                            const float* sc, int n0, int tid) {
    const int s  = kt % STAGES;
    const int k0 = kt * BK;
    const int g  = k0 >> 7;          // quant group (BK=64 within one 128-group)
    // A: 128 rows x 128B = 1024 chunks, 4 per thread
    uint32_t aBase = sb + OFF_A + s * 16384;
#pragma unroll
    for (int it = 0; it < 4; ++it) {
        int chunk = tid + it * 256;
        int r = chunk >> 3, c = chunk & 7;
        cp_async16(aBase + SWZ((uint32_t)(r * 128 + c * 16)),
                   gA + (size_t)r * IN_F + k0 + c * 8);
    }
    // raw qweight: 8 kp-rows x 128 ints = 256 chunks, 1 per thread
    {
        int kp = tid >> 5, n4 = tid & 31;
        cp_async16(sb + OFF_RAW + s * 4096 + tid * 16,
                   qw + (size_t)(k0 / 8 + kp) * OUT_F + n0 + n4 * 4);
    }
    // scales: 128 fp32 = 32 chunks
    if (tid < 32)
        cp_async16(sb + OFF_SC + s * 512 + tid * 16, sc + (size_t)g * OUT_F + n0 + tid * 4);
    // qzeros: 16 ints = 4 chunks
    if (tid >= 32 && tid < 36) {
        int c = tid - 32;
        cp_async16(sb + OFF_QZ + s * 64 + c * 16, qz + (size_t)g * (OUT_F / 8) + (n0 >> 3) + c * 4);
    }
    cp_commit();
}

// Dequant stage kt: read raw/scales/zeros from SMEM, write fp16 B tile (swizzled).
__device__ __forceinline__ void dequant_stage(int kt, uint32_t sb, const char* smem, int tid) {
    const int s = kt % STAGES;
    const uint32_t* raw = (const uint32_t*)(smem + OFF_RAW + s * 4096);
    const float*    scb = (const float*)(smem + OFF_SC + s * 512);
    const uint32_t* qzb = (const uint32_t*)(smem + OFF_QZ + s * 64);
    uint32_t bBase = sb + OFF_B + s * 16384;

    const int n   = tid & 127;
    const int kp0 = (tid >> 7) * 4;     // 0 or 4
    float s_f = scb[n];
    int   z   = (int)((qzb[n >> 3] >> ((n & 7) * 4)) & 15u);
    float nsz = -s_f * (float)z;
#pragma unroll
    for (int i = 0; i < 4; ++i) {
        int kp = kp0 + i;
        uint32_t w = raw[kp * 128 + n];
        union { __half2 h[4]; uint32_t u[4]; } r;
#pragma unroll
        for (int j = 0; j < 4; ++j) {
            float v0 = fmaf(s_f, (float)((w >> (8 * j)) & 15u), nsz);
            float v1 = fmaf(s_f, (float)((w >> (8 * j + 4)) & 15u), nsz);
            r.h[j] = __floats2half2_rn(v0, v1);
        }
        sts128(bBase + SWZ((uint32_t)(n * 128 + kp * 16)), r.u[0], r.u[1], r.u[2], r.u[3]);
    }
}

__global__ void __launch_bounds__(256, 2) gemm_kernel(const int* __restrict__ qw,
                                                      const int* __restrict__ qz,
                                                      const float* __restrict__ sc,
                                                      const float* __restrict__ bias,
                                                      float* __restrict__ out) {
    extern __shared__ char dynsmem_raw[];
    const int tid = threadIdx.x;
    const int wid = tid >> 5;
    const int lid = tid & 31;
    const int wm = wid & 3;       // 4 m-warps (32 rows each)
    const int wn = wid >> 2;      // 2 n-warps (64 cols each)
    const int m0 = blockIdx.x * BM;   // 64 m-tiles
    const int n0 = blockIdx.y * BN;   // 86 n-tiles

    uint32_t sb0 = smem_u32(dynsmem_raw);
    uint32_t sb  = (sb0 + 1023) & ~1023u;            // 1024-aligned base
    const char* smem = dynsmem_raw + (sb - sb0);

    const __half* gA = g_X + (size_t)m0 * IN_F;

    float acc[2][8][4];
#pragma unroll
    for (int mi = 0; mi < 2; ++mi)
#pragma unroll
        for (int ni = 0; ni < 8; ++ni)
#pragma unroll
            for (int q = 0; q < 4; ++q) acc[mi][ni][q] = 0.0f;

    // per-lane ldmatrix components
    const int aRow = wm * 32 + (lid & 15);            // + mi*16
    const int aChk = lid >> 4;                        // + 2*kk
    const int bRow = wn * 64 + (lid & 7) + ((lid >> 4) & 1) * 8;  // + nj*16
    const int bChk = (lid >> 3) & 1;                  // + 2*kk

    // ---- prologue ----
    issue_group(0, sb, gA, qw, qz, sc, n0, tid);
    issue_group(1, sb, gA, qw, qz, sc, n0, tid);
    cp_wait<1>();            // stage 0 landed
    __syncthreads();
    dequant_stage(0, sb, smem, tid);
    issue_group(2, sb, gA, qw, qz, sc, n0, tid);
    __syncthreads();

    for (int j = 0; j < KITERS; ++j) {
        // ---- MMA on stage j ----
        const uint32_t aT = sb + OFF_A + (j % STAGES) * 16384;
        const uint32_t bT = sb + OFF_B + (j % STAGES) * 16384;
#pragma unroll
        for (int kk = 0; kk < BK / 16; ++kk) {
            uint32_t a[2][4];
#pragma unroll
            for (int mi = 0; mi < 2; ++mi) {
                uint32_t ad = aT + SWZ((uint32_t)((aRow + mi * 16) * 128 + (2 * kk + aChk) * 16));
                ldsm_x4(a[mi][0], a[mi][1], a[mi][2], a[mi][3], ad);
            }
            uint32_t b[8][2];
#pragma unroll
            for (int nj = 0; nj < 4; ++nj) {
                uint32_t bd = bT + SWZ((uint32_t)((bRow + nj * 16) * 128 + (2 * kk + bChk) * 16));
                uint32_t r0, r1, r2, r3;
                ldsm_x4(r0, r1, r2, r3, bd);
                b[2 * nj][0] = r0;     b[2 * nj][1] = r1;
                b[2 * nj + 1][0] = r2; b[2 * nj + 1][1] = r3;
            }
#pragma unroll
            for (int mi = 0; mi < 2; ++mi)
#pragma unroll
                for (int ni = 0; ni < 8; ++ni)
                    mma16816(acc[mi][ni], a[mi], b[ni]);
        }

        // ---- prepare stage j+1 ----
        if (j + 1 < KITERS) {
            if (j + 2 < KITERS) cp_wait<1>();   // stage j+1 landed (j+2 may be in flight)
            else                cp_wait<0>();
            __syncthreads();                    // all MMA(j) done; raw(j+1) visible
            dequant_stage(j + 1, sb, smem, tid);
            if (j + 3 < KITERS) issue_group(j + 3, sb, gA, qw, qz, sc, n0, tid);
            __syncthreads();                    // B(j+1) visible
        }
    }

    // ---- epilogue: direct stores with bias ----
    const int mw = m0 + wm * 32;
    const int nw = n0 + wn * 64;
    const int rsub = lid >> 2;
    const int csub = (lid & 3) * 2;
#pragma unroll
    for (int mi = 0; mi < 2; ++mi) {
#pragma unroll
        for (int ni = 0; ni < 8; ++ni) {
            int col = nw + ni * 8 + csub;
            float2 bv = *(const float2*)(bias + col);
            int r0 = mw + mi * 16 + rsub;
            float2 v0 = { acc[mi][ni][0] + bv.x, acc[mi][ni][1] + bv.y };
            *(float2*)(out + (size_t)r0 * OUT_F + col) = v0;
            float2 v1 = { acc[mi][ni][2] + bv.x, acc[mi][ni][3] + bv.y };
            *(float2*)(out + (size_t)(r0 + 8) * OUT_F + col) = v1;
        }
    }
}

// ---------------- launch ----------------
extern "C" void kernel_launch(void* const* d_in, const int* in_sizes, int n_in,
                              void* d_out, int out_size) {
    const float* x    = (const float*)d_in[0];
    const int*   qw   = (const int*)d_in[1];
    const int*   qz   = (const int*)d_in[2];
    const float* sc   = (const float*)d_in[3];
    const float* bias = (const float*)d_in[4];
    float* out = (float*)d_out;

    cudaFuncSetAttribute(gemm_kernel, cudaFuncAttributeMaxDynamicSharedMemorySize, SMEM_BYTES);

    // 1) x -> fp16
    {
        int total = (int)(((size_t)TOKENS * IN_F) / 4);  // 8,388,608
        xconv_kernel<<<total / 256, 256>>>(x);
    }
    // 2) fused dequant + GEMM + bias
    {
        dim3 grid(TOKENS / BM, OUT_F / BN);  // (64, 86)
        gemm_kernel<<<grid, 256, SMEM_BYTES>>>(qw, qz, sc, bias, out);
    }
}

// round 4
// speedup vs baseline: 1.1077x; 1.1077x over previous
#include <cuda_runtime.h>
#include <cuda_fp16.h>
#include <cstdint>
#include <cstddef>

// ---------------- problem constants ----------------
#define TOKENS 8192
#define IN_F   4096
#define OUT_F  11008

// ---------------- GEMM tiling ----------------
#define BM 128
#define BN 128
#define BK 64
#define STAGES 3
#define KITERS (IN_F / BK)          // 64
#define NTHREADS 128                // 4 warps, 2x2 grid, 64x64 warp tiles

// SMEM layout (byte offsets from 1024-aligned base)
#define OFF_A      0                         // 3 x 16384
#define OFF_B      (OFF_A + STAGES * 16384)  // 3 x 16384
#define OFF_RAW    (OFF_B + STAGES * 16384)  // 3 x 4096  (8 kp-rows x 128 n int32)
#define OFF_SC     (OFF_RAW + STAGES * 4096) // 3 x 512   (128 scales fp32)
#define OFF_QZ     (OFF_SC + STAGES * 512)   // 3 x 64    (16 int32)
#define SMEM_USED  (OFF_QZ + STAGES * 64)    // 112320
#define SMEM_BYTES (SMEM_USED + 1024)        // 113344 -> 2 CTAs/SM

// ---------------- scratch (static device global; no allocation) ----------------
// x as fp16, k-permuted within each octet: pos p of octet holds x[k_oct*8 + perm[p]],
// perm = [0,4,1,5,2,6,3,7]. B tiles use the same permutation -> GEMM invariant.
__device__ __align__(1024) __half g_X[(size_t)TOKENS * IN_F]; // 67 MB

// ---------------- PTX helpers (baseline sm_80+ only) ----------------
__device__ __forceinline__ uint32_t smem_u32(const void* p) {
    uint32_t a;
    asm("{ .reg .u64 t; cvta.to.shared.u64 t, %1; cvt.u32.u64 %0, t; }" : "=r"(a) : "l"(p));
    return a;
}
__device__ __forceinline__ void cp_async16(uint32_t dst, const void* src) {
    asm volatile("cp.async.cg.shared.global [%0], [%1], 16;" :: "r"(dst), "l"(src) : "memory");
}
__device__ __forceinline__ void cp_commit() {
    asm volatile("cp.async.commit_group;" ::: "memory");
}
template <int N> __device__ __forceinline__ void cp_wait() {
    asm volatile("cp.async.wait_group %0;" :: "n"(N) : "memory");
}
__device__ __forceinline__ void ldsm_x4(uint32_t& r0, uint32_t& r1, uint32_t& r2, uint32_t& r3,
                                        uint32_t addr) {
    asm volatile("ldmatrix.sync.aligned.m8n8.x4.shared.b16 {%0,%1,%2,%3}, [%4];"
                 : "=r"(r0), "=r"(r1), "=r"(r2), "=r"(r3) : "r"(addr));
}
__device__ __forceinline__ void sts128(uint32_t addr, uint32_t r0, uint32_t r1,
                                       uint32_t r2, uint32_t r3) {
    asm volatile("st.shared.v4.b32 [%0], {%1,%2,%3,%4};"
                 :: "r"(addr), "r"(r0), "r"(r1), "r"(r2), "r"(r3) : "memory");
}
__device__ __forceinline__ void mma16816(float* c, const uint32_t* a, const uint32_t* b) {
    asm volatile(
        "mma.sync.aligned.m16n8k16.row.col.f32.f16.f16.f32 "
        "{%0,%1,%2,%3}, {%4,%5,%6,%7}, {%8,%9}, {%0,%1,%2,%3};"
        : "+f"(c[0]), "+f"(c[1]), "+f"(c[2]), "+f"(c[3])
        : "r"(a[0]), "r"(a[1]), "r"(a[2]), "r"(a[3]), "r"(b[0]), "r"(b[1]));
}

// SW128 swizzle on byte offset within a tile (128B rows)
#define SWZ(o) ((o) ^ (((o) >> 3) & 0x70))

// ---------------- kernel 1: x fp32 -> fp16, octet-permuted ----------------
__global__ void __launch_bounds__(256) xconv_kernel(const float* __restrict__ x) {
    size_t i = (size_t)blockIdx.x * blockDim.x + threadIdx.x;  // one octet (8 floats) each
    const float4* p = (const float4*)(x + i * 8);
    float4 v0 = p[0];
    float4 v1 = p[1];
    union { __half2 h[4]; uint4 u; } r;
    r.h[0] = __floats2half2_rn(v0.x, v1.x);  // (f0, f4)
    r.h[1] = __floats2half2_rn(v0.y, v1.y);  // (f1, f5)
    r.h[2] = __floats2half2_rn(v0.z, v1.z);  // (f2, f6)
    r.h[3] = __floats2half2_rn(v0.w, v1.w);  // (f3, f7)
    ((uint4*)g_X)[i] = r.u;
}

// ---------------- kernel 2: fused dequant + pipelined HMMA GEMM ----------------
__device__ __forceinline__ void issue_group(int kt, uint32_t sb, const __half* gA,
                                            const int* qw, const int* qz,
                                            const float* sc, int n0, int tid) {
    const int s  = kt % STAGES;
    const int k0 = kt * BK;
    const int g  = k0 >> 7;          // quant group (BK=64 inside one 128-group)
    // A: 128 rows x 128B = 1024 chunks, 8 per thread
    uint32_t aBase = sb + OFF_A + s * 16384;
#pragma unroll
    for (int it = 0; it < 8; ++it) {
        int chunk = tid + it * NTHREADS;
        int r = chunk >> 3, c = chunk & 7;
        cp_async16(aBase + SWZ((uint32_t)(r * 128 + c * 16)),
                   gA + (size_t)r * IN_F + k0 + c * 8);
    }
    // raw qweight: 8 kp-rows x 128 ints = 256 chunks, 2 per thread
#pragma unroll
    for (int it = 0; it < 2; ++it) {
        int chunk = tid + it * NTHREADS;
        int kp = chunk >> 5, n4 = chunk & 31;
        cp_async16(sb + OFF_RAW + s * 4096 + chunk * 16,
                   qw + (size_t)(k0 / 8 + kp) * OUT_F + n0 + n4 * 4);
    }
    // scales: 128 fp32 = 32 chunks
    if (tid < 32)
        cp_async16(sb + OFF_SC + s * 512 + tid * 16, sc + (size_t)g * OUT_F + n0 + tid * 4);
    // qzeros: 16 ints = 4 chunks
    if (tid >= 32 && tid < 36) {
        int c = tid - 32;
        cp_async16(sb + OFF_QZ + s * 64 + c * 16, qz + (size_t)g * (OUT_F / 8) + (n0 >> 3) + c * 4);
    }
    cp_commit();
}

// Dequant stage kt via fp16 LOP3 trick; thread t owns column n=t, 8 packed words.
__device__ __forceinline__ void dequant_stage(int kt, uint32_t sb, const char* smem, int tid) {
    const int s = kt % STAGES;
    const uint32_t* raw = (const uint32_t*)(smem + OFF_RAW + s * 4096);
    const float*    scb = (const float*)(smem + OFF_SC + s * 512);
    const uint32_t* qzb = (const uint32_t*)(smem + OFF_QZ + s * 64);
    uint32_t bBase = sb + OFF_B + s * 16384;

    const int n = tid;  // 0..127
    float s_f = scb[n];
    int   z   = (int)((qzb[n >> 3] >> ((n & 7) * 4)) & 15u);
    __half2 s2  = __float2half2_rn(s_f);
    __half2 hz2 = __float2half2_rn(1024.0f + (float)z);  // exact in fp16
#pragma unroll
    for (int kp = 0; kp < 8; ++kp) {
        uint32_t w = raw[kp * 128 + n];
        // (q | 0x6400) as half2 = 1024 + q exactly; pairs are (j, j+4) -> permuted layout
        uint32_t q0 = (w & 0x000F000Fu) | 0x64006400u;
        uint32_t q1 = ((w >> 4)  & 0x000F000Fu) | 0x64006400u;
        uint32_t q2 = ((w >> 8)  & 0x000F000Fu) | 0x64006400u;
        uint32_t q3 = ((w >> 12) & 0x000F000Fu) | 0x64006400u;
        union { __half2 h; uint32_t u; } r0, r1, r2, r3;
        r0.h = __hmul2(__hsub2(*(__half2*)&q0, hz2), s2);  // exact sub, one rounding
        r1.h = __hmul2(__hsub2(*(__half2*)&q1, hz2), s2);
        r2.h = __hmul2(__hsub2(*(__half2*)&q2, hz2), s2);
        r3.h = __hmul2(__hsub2(*(__half2*)&q3, hz2), s2);
        sts128(bBase + SWZ((uint32_t)(n * 128 + kp * 16)), r0.u, r1.u, r2.u, r3.u);
    }
}

__global__ void __launch_bounds__(NTHREADS, 2) gemm_kernel(const int* __restrict__ qw,
                                                           const int* __restrict__ qz,
                                                           const float* __restrict__ sc,
                                                           const float* __restrict__ bias,
                                                           float* __restrict__ out) {
    extern __shared__ char dynsmem_raw[];
    const int tid = threadIdx.x;
    const int wid = tid >> 5;
    const int lid = tid & 31;
    const int wm = wid & 1;       // 2 m-warps (64 rows each)
    const int wn = wid >> 1;      // 2 n-warps (64 cols each)
    const int m0 = blockIdx.x * BM;   // 64 m-tiles
    const int n0 = blockIdx.y * BN;   // 86 n-tiles

    uint32_t sb0 = smem_u32(dynsmem_raw);
    uint32_t sb  = (sb0 + 1023) & ~1023u;            // 1024-aligned base
    const char* smem = dynsmem_raw + (sb - sb0);

    const __half* gA = g_X + (size_t)m0 * IN_F;

    float acc[4][8][4];
#pragma unroll
    for (int mi = 0; mi < 4; ++mi)
#pragma unroll
        for (int ni = 0; ni < 8; ++ni)
#pragma unroll
            for (int q = 0; q < 4; ++q) acc[mi][ni][q] = 0.0f;

    // per-lane ldmatrix components
    const int aRow = wm * 64 + (lid & 15);            // + mi*16
    const int aChk = lid >> 4;                        // + 2*kk
    const int bRow = wn * 64 + (lid & 7) + ((lid >> 4) & 1) * 8;  // + nj*16
    const int bChk = (lid >> 3) & 1;                  // + 2*kk

    // ---- prologue ----
    issue_group(0, sb, gA, qw, qz, sc, n0, tid);
    issue_group(1, sb, gA, qw, qz, sc, n0, tid);
    cp_wait<1>();            // stage 0 landed
    __syncthreads();
    dequant_stage(0, sb, smem, tid);
    issue_group(2, sb, gA, qw, qz, sc, n0, tid);
    __syncthreads();

    for (int j = 0; j < KITERS; ++j) {
        // ---- MMA on stage j ----
        const uint32_t aT = sb + OFF_A + (j % STAGES) * 16384;
        const uint32_t bT = sb + OFF_B + (j % STAGES) * 16384;
#pragma unroll
        for (int kk = 0; kk < BK / 16; ++kk) {
            uint32_t a[4][4];
#pragma unroll
            for (int mi = 0; mi < 4; ++mi) {
                uint32_t ad = aT + SWZ((uint32_t)((aRow + mi * 16) * 128 + (2 * kk + aChk) * 16));
                ldsm_x4(a[mi][0], a[mi][1], a[mi][2], a[mi][3], ad);
            }
            uint32_t b[8][2];
#pragma unroll
            for (int nj = 0; nj < 4; ++nj) {
                uint32_t bd = bT + SWZ((uint32_t)((bRow + nj * 16) * 128 + (2 * kk + bChk) * 16));
                uint32_t r0, r1, r2, r3;
                ldsm_x4(r0, r1, r2, r3, bd);
                b[2 * nj][0] = r0;     b[2 * nj][1] = r1;
                b[2 * nj + 1][0] = r2; b[2 * nj + 1][1] = r3;
            }
#pragma unroll
            for (int mi = 0; mi < 4; ++mi)
#pragma unroll
                for (int ni = 0; ni < 8; ++ni)
                    mma16816(acc[mi][ni], a[mi], b[ni]);
        }

        // ---- prepare stage j+1 ----
        if (j + 1 < KITERS) {
            if (j + 2 < KITERS) cp_wait<1>();   // stage j+1 landed (j+2 in flight)
            else                cp_wait<0>();
            __syncthreads();                    // raw(j+1) visible; MMA(j) reads done
            dequant_stage(j + 1, sb, smem, tid);
            if (j + 3 < KITERS) issue_group(j + 3, sb, gA, qw, qz, sc, n0, tid);
            __syncthreads();                    // B(j+1) visible
        }
    }

    // ---- epilogue: direct stores with bias ----
    const int mw = m0 + wm * 64;
    const int nw = n0 + wn * 64;
    const int rsub = lid >> 2;
    const int csub = (lid & 3) * 2;
#pragma unroll
    for (int mi = 0; mi < 4; ++mi) {
#pragma unroll
        for (int ni = 0; ni < 8; ++ni) {
            int col = nw + ni * 8 + csub;
            float2 bv = *(const float2*)(bias + col);
            int r0 = mw + mi * 16 + rsub;
            float2 v0 = { acc[mi][ni][0] + bv.x, acc[mi][ni][1] + bv.y };
            *(float2*)(out + (size_t)r0 * OUT_F + col) = v0;
            float2 v1 = { acc[mi][ni][2] + bv.x, acc[mi][ni][3] + bv.y };
            *(float2*)(out + (size_t)(r0 + 8) * OUT_F + col) = v1;
        }
    }
}

// ---------------- launch ----------------
extern "C" void kernel_launch(void* const* d_in, const int* in_sizes, int n_in,
                              void* d_out, int out_size) {
    const float* x    = (const float*)d_in[0];
    const int*   qw   = (const int*)d_in[1];
    const int*   qz   = (const int*)d_in[2];
    const float* sc   = (const float*)d_in[3];
    const float* bias = (const float*)d_in[4];
    float* out = (float*)d_out;

    cudaFuncSetAttribute(gemm_kernel, cudaFuncAttributeMaxDynamicSharedMemorySize, SMEM_BYTES);

    // 1) x -> fp16 (octet-permuted)
    {
        int total = (int)(((size_t)TOKENS * IN_F) / 8);  // 4,194,304 octets
        xconv_kernel<<<total / 256, 256>>>(x);
    }
    // 2) fused dequant + GEMM + bias
    {
        dim3 grid(TOKENS / BM, OUT_F / BN);  // (64, 86)
        gemm_kernel<<<grid, NTHREADS, SMEM_BYTES>>>(qw, qz, sc, bias, out);
    }
}

// round 5
// speedup vs baseline: 1.1452x; 1.0339x over previous
#include <cuda_runtime.h>
#include <cuda_fp16.h>
#include <cstdint>
#include <cstddef>

// ---------------- problem constants ----------------
#define TOKENS 8192
#define IN_F   4096
#define OUT_F  11008

// ---------------- GEMM tiling ----------------
#define BM 128
#define BN 128
#define BK 64
#define STAGES 3
#define KITERS (IN_F / BK)          // 64
#define NTHREADS 128                // 4 warps, 2x2 grid, 64x64 warp tiles

// SMEM layout (byte offsets from 1024-aligned base)
#define OFF_A      0                         // 3 x 16384
#define OFF_B      (OFF_A + STAGES * 16384)  // 3 x 16384
#define OFF_RAW    (OFF_B + STAGES * 16384)  // 3 x 4096  (raw[kp*128+n], 4B)
#define OFF_SC     (OFF_RAW + STAGES * 4096) // 3 x 512   (per-thread scale fp32)
#define OFF_QZ     (OFF_SC + STAGES * 512)   // 3 x 512   (per-thread qz word copy)
#define SMEM_USED  (OFF_QZ + STAGES * 512)   // 113664
#define SMEM_BYTES (SMEM_USED + 1024)        // 114688 -> 2 CTAs/SM (229376 <= 233472)

// ---------------- scratch (static device global; no allocation) ----------------
// x fp16, octet-permuted: pos p of each 8-k octet holds x[oct*8 + perm[p]],
// perm = [0,4,1,5,2,6,3,7]; B dequant emits the same permutation -> GEMM invariant.
__device__ __align__(1024) __half g_X[(size_t)TOKENS * IN_F]; // 67 MB

// ---------------- PTX helpers (baseline sm_80+ only) ----------------
__device__ __forceinline__ uint32_t smem_u32(const void* p) {
    uint32_t a;
    asm("{ .reg .u64 t; cvta.to.shared.u64 t, %1; cvt.u32.u64 %0, t; }" : "=r"(a) : "l"(p));
    return a;
}
__device__ __forceinline__ void cp_async16(uint32_t dst, const void* src) {
    asm volatile("cp.async.cg.shared.global [%0], [%1], 16;" :: "r"(dst), "l"(src) : "memory");
}
__device__ __forceinline__ void cp_async4(uint32_t dst, const void* src) {
    asm volatile("cp.async.ca.shared.global [%0], [%1], 4;" :: "r"(dst), "l"(src) : "memory");
}
__device__ __forceinline__ void cp_commit() {
    asm volatile("cp.async.commit_group;" ::: "memory");
}
template <int N> __device__ __forceinline__ void cp_wait() {
    asm volatile("cp.async.wait_group %0;" :: "n"(N) : "memory");
}
__device__ __forceinline__ void ldsm_x4(uint32_t& r0, uint32_t& r1, uint32_t& r2, uint32_t& r3,
                                        uint32_t addr) {
    asm volatile("ldmatrix.sync.aligned.m8n8.x4.shared.b16 {%0,%1,%2,%3}, [%4];"
                 : "=r"(r0), "=r"(r1), "=r"(r2), "=r"(r3) : "r"(addr));
}
__device__ __forceinline__ void sts128(uint32_t addr, uint32_t r0, uint32_t r1,
                                       uint32_t r2, uint32_t r3) {
    asm volatile("st.shared.v4.b32 [%0], {%1,%2,%3,%4};"
                 :: "r"(addr), "r"(r0), "r"(r1), "r"(r2), "r"(r3) : "memory");
}
__device__ __forceinline__ void mma16816(float* c, const uint32_t* a, const uint32_t* b) {
    asm volatile(
        "mma.sync.aligned.m16n8k16.row.col.f32.f16.f16.f32 "
        "{%0,%1,%2,%3}, {%4,%5,%6,%7}, {%8,%9}, {%0,%1,%2,%3};"
        : "+f"(c[0]), "+f"(c[1]), "+f"(c[2]), "+f"(c[3])
        : "r"(a[0]), "r"(a[1]), "r"(a[2]), "r"(a[3]), "r"(b[0]), "r"(b[1]));
}

// SW128 swizzle on byte offset within a tile (128B rows)
#define SWZ(o) ((o) ^ (((o) >> 3) & 0x70))

// ---------------- kernel 1: x fp32 -> fp16, octet-permuted ----------------
__global__ void __launch_bounds__(256) xconv_kernel(const float* __restrict__ x) {
    size_t i = (size_t)blockIdx.x * blockDim.x + threadIdx.x;  // one octet (8 floats) each
    const float4* p = (const float4*)(x + i * 8);
    float4 v0 = p[0];
    float4 v1 = p[1];
    union { __half2 h[4]; uint4 u; } r;
    r.h[0] = __floats2half2_rn(v0.x, v1.x);
    r.h[1] = __floats2half2_rn(v0.y, v1.y);
    r.h[2] = __floats2half2_rn(v0.z, v1.z);
    r.h[3] = __floats2half2_rn(v0.w, v1.w);
    ((uint4*)g_X)[i] = r.u;
}

// ---------------- kernel 2: fused dequant + pipelined HMMA GEMM ----------------
// Each thread cp.asyncs its OWN dequant inputs (column n = tid): 8 raw words,
// 1 scale, 1 qzero word. After wait_group they are self-visible -> no barrier
// needed before dequant.
__device__ __forceinline__ void issue_group(int kt, uint32_t sb, const __half* gA,
                                            const int* qw, const int* qz,
                                            const float* sc, int n0, int tid) {
    const int s  = kt % STAGES;
    const int k0 = kt * BK;
    const int g  = k0 >> 7;          // quant group (BK=64 inside one 128-group)
    // A: 128 rows x 128B = 1024 chunks, 8 per thread
    uint32_t aBase = sb + OFF_A + s * 16384;
#pragma unroll
    for (int it = 0; it < 8; ++it) {
        int chunk = tid + it * NTHREADS;
        int r = chunk >> 3, c = chunk & 7;
        cp_async16(aBase + SWZ((uint32_t)(r * 128 + c * 16)),
                   gA + (size_t)r * IN_F + k0 + c * 8);
    }
    // raw qweight: thread t owns column n0+t -> 8 words (coalesced across warp)
    const int n = tid;
    uint32_t rawBase = sb + OFF_RAW + s * 4096;
#pragma unroll
    for (int kp = 0; kp < 8; ++kp)
        cp_async4(rawBase + (uint32_t)(kp * 512 + n * 4),
                  qw + (size_t)(k0 / 8 + kp) * OUT_F + n0 + n);
    // own scale + own qzero-word copy
    cp_async4(sb + OFF_SC + s * 512 + n * 4, sc + (size_t)g * OUT_F + n0 + n);
    cp_async4(sb + OFF_QZ + s * 512 + n * 4, qz + (size_t)g * (OUT_F / 8) + ((n0 + n) >> 3));
    cp_commit();
}

// Dequant stage kt via fp16 LOP3 trick; thread t owns column n=t (self-owned data).
__device__ __forceinline__ void dequant_stage(int kt, uint32_t sb, const char* smem, int tid) {
    const int s = kt % STAGES;
    const uint32_t* raw = (const uint32_t*)(smem + OFF_RAW + s * 4096);
    const float*    scb = (const float*)(smem + OFF_SC + s * 512);
    const uint32_t* qzb = (const uint32_t*)(smem + OFF_QZ + s * 512);
    uint32_t bBase = sb + OFF_B + s * 16384;

    const int n = tid;  // 0..127
    float s_f = scb[n];
    int   z   = (int)((qzb[n] >> ((n & 7) * 4)) & 15u);
    __half2 s2  = __float2half2_rn(s_f);
    __half2 hz2 = __float2half2_rn(1024.0f + (float)z);  // exact in fp16
#pragma unroll
    for (int kp = 0; kp < 8; ++kp) {
        uint32_t w = raw[kp * 128 + n];
        uint32_t q0 = (w & 0x000F000Fu) | 0x64006400u;
        uint32_t q1 = ((w >> 4)  & 0x000F000Fu) | 0x64006400u;
        uint32_t q2 = ((w >> 8)  & 0x000F000Fu) | 0x64006400u;
        uint32_t q3 = ((w >> 12) & 0x000F000Fu) | 0x64006400u;
        union { __half2 h; uint32_t u; } r0, r1, r2, r3;
        r0.h = __hmul2(__hsub2(*(__half2*)&q0, hz2), s2);
        r1.h = __hmul2(__hsub2(*(__half2*)&q1, hz2), s2);
        r2.h = __hmul2(__hsub2(*(__half2*)&q2, hz2), s2);
        r3.h = __hmul2(__hsub2(*(__half2*)&q3, hz2), s2);
        sts128(bBase + SWZ((uint32_t)(n * 128 + kp * 16)), r0.u, r1.u, r2.u, r3.u);
    }
}

__global__ void __launch_bounds__(NTHREADS, 2) gemm_kernel(const int* __restrict__ qw,
                                                           const int* __restrict__ qz,
                                                           const float* __restrict__ sc,
                                                           const float* __restrict__ bias,
                                                           float* __restrict__ out) {
    extern __shared__ char dynsmem_raw[];
    const int tid = threadIdx.x;
    const int wid = tid >> 5;
    const int lid = tid & 31;
    const int wm = wid & 1;       // 2 m-warps (64 rows each)
    const int wn = wid >> 1;      // 2 n-warps (64 cols each)
    const int m0 = blockIdx.x * BM;   // 64 m-tiles
    const int n0 = blockIdx.y * BN;   // 86 n-tiles

    uint32_t sb0 = smem_u32(dynsmem_raw);
    uint32_t sb  = (sb0 + 1023) & ~1023u;            // 1024-aligned base
    const char* smem = dynsmem_raw + (sb - sb0);

    const __half* gA = g_X + (size_t)m0 * IN_F;

    float acc[4][8][4];
#pragma unroll
    for (int mi = 0; mi < 4; ++mi)
#pragma unroll
        for (int ni = 0; ni < 8; ++ni)
#pragma unroll
            for (int q = 0; q < 4; ++q) acc[mi][ni][q] = 0.0f;

    // per-lane ldmatrix components
    const int aRow = wm * 64 + (lid & 15);            // + mi*16
    const int aChk = lid >> 4;                        // + 2*kk
    const int bRow = wn * 64 + (lid & 7) + ((lid >> 4) & 1) * 8;  // + nj*16
    const int bChk = (lid >> 3) & 1;                  // + 2*kk

    // ---- prologue ----
    issue_group(0, sb, gA, qw, qz, sc, n0, tid);
    issue_group(1, sb, gA, qw, qz, sc, n0, tid);
    issue_group(2, sb, gA, qw, qz, sc, n0, tid);
    cp_wait<2>();            // stage 0 landed (self-visible)
    dequant_stage(0, sb, smem, tid);
    __syncthreads();         // A(0), B(0) visible to all

    for (int j = 0; j < KITERS; ++j) {
        // ---- MMA on stage j (A(j), B(j) visible since last barrier) ----
        const uint32_t aT = sb + OFF_A + (j % STAGES) * 16384;
        const uint32_t bT = sb + OFF_B + (j % STAGES) * 16384;
#pragma unroll
        for (int kk = 0; kk < BK / 16; ++kk) {
            uint32_t a[4][4];
#pragma unroll
            for (int mi = 0; mi < 4; ++mi) {
                uint32_t ad = aT + SWZ((uint32_t)((aRow + mi * 16) * 128 + (2 * kk + aChk) * 16));
                ldsm_x4(a[mi][0], a[mi][1], a[mi][2], a[mi][3], ad);
            }
            uint32_t b[8][2];
#pragma unroll
            for (int nj = 0; nj < 4; ++nj) {
                uint32_t bd = bT + SWZ((uint32_t)((bRow + nj * 16) * 128 + (2 * kk + bChk) * 16));
                uint32_t r0, r1, r2, r3;
                ldsm_x4(r0, r1, r2, r3, bd);
                b[2 * nj][0] = r0;     b[2 * nj][1] = r1;
                b[2 * nj + 1][0] = r2; b[2 * nj + 1][1] = r3;
            }
#pragma unroll
            for (int mi = 0; mi < 4; ++mi)
#pragma unroll
                for (int ni = 0; ni < 8; ++ni)
                    mma16816(acc[mi][ni], a[mi], b[ni]);
        }

        // ---- prepare stage j+1: dequant own data (no barrier needed first) ----
        if (j + 1 < KITERS) {
            if (j + 2 < KITERS) cp_wait<1>();   // group j+1 landed (self)
            else                cp_wait<0>();
            dequant_stage(j + 1, sb, smem, tid);  // writes B slot (j+1)%3
            __syncthreads();  // publishes B(j+1)/A(j+1); all MMA(j) reads done
            if (j + 3 < KITERS)
                issue_group(j + 3, sb, gA, qw, qz, sc, n0, tid);  // reuses slot j%3 safely
        }
    }

    // ---- epilogue: direct stores with bias ----
    const int mw = m0 + wm * 64;
    const int nw = n0 + wn * 64;
    const int rsub = lid >> 2;
    const int csub = (lid & 3) * 2;
#pragma unroll
    for (int mi = 0; mi < 4; ++mi) {
#pragma unroll
        for (int ni = 0; ni < 8; ++ni) {
            int col = nw + ni * 8 + csub;
            float2 bv = *(const float2*)(bias + col);
            int r0 = mw + mi * 16 + rsub;
            float2 v0 = { acc[mi][ni][0] + bv.x, acc[mi][ni][1] + bv.y };
            *(float2*)(out + (size_t)r0 * OUT_F + col) = v0;
            float2 v1 = { acc[mi][ni][2] + bv.x, acc[mi][ni][3] + bv.y };
            *(float2*)(out + (size_t)(r0 + 8) * OUT_F + col) = v1;
        }
    }
}

// ---------------- launch ----------------
extern "C" void kernel_launch(void* const* d_in, const int* in_sizes, int n_in,
                              void* d_out, int out_size) {
    const float* x    = (const float*)d_in[0];
    const int*   qw   = (const int*)d_in[1];
    const int*   qz   = (const int*)d_in[2];
    const float* sc   = (const float*)d_in[3];
    const float* bias = (const float*)d_in[4];
    float* out = (float*)d_out;

    cudaFuncSetAttribute(gemm_kernel, cudaFuncAttributeMaxDynamicSharedMemorySize, SMEM_BYTES);

    // 1) x -> fp16 (octet-permuted)
    {
        int total = (int)(((size_t)TOKENS * IN_F) / 8);  // 4,194,304 octets
        xconv_kernel<<<total / 256, 256>>>(x);
    }
    // 2) fused dequant + GEMM + bias
    {
        dim3 grid(TOKENS / BM, OUT_F / BN);  // (64, 86)
        gemm_kernel<<<grid, NTHREADS, SMEM_BYTES>>>(qw, qz, sc, bias, out);
    }
}